// round 8
// baseline (speedup 1.0000x reference)
#include <cuda_runtime.h>
#include <cstdint>

#define C_   16
#define H_   64
#define W_   64
#define KL_  25
#define O_   32
#define HW_  4096

// Fragment-ordered idx: [c][tile(32)][warp(8)][kstep(4)][lane(32)][4 x int16]
// value = window-relative BYTE offset (word*8) in [0,3072], 3072 = zero-pad sentinel.
__device__ __align__(16) unsigned short g_idx16[C_ * 32 * 8 * 4 * 32 * 4];  // 4 MB
// Pre-built tf32 B fragments: [(c*4+s)*2+h][lane][4 words] = 64 KB
__device__ __align__(16) uint32_t g_bfrag[32768];

__device__ __forceinline__ uint32_t cvt_tf32(float f) {
    uint32_t r;
    asm("cvt.rna.tf32.f32 %0, %1;" : "=r"(r) : "f"(f));
    return r;
}
__device__ __forceinline__ uint32_t smem_u32(const void* p) {
    uint32_t a;
    asm("{ .reg .u64 t; cvta.to.shared.u64 t, %1; cvt.u32.u64 %0, t; }" : "=r"(a) : "l"(p));
    return a;
}
__device__ __forceinline__ void cpasync16(uint32_t dst, const void* src) {
    asm volatile("cp.async.ca.shared.global [%0], [%1], 16;" :: "r"(dst), "l"(src) : "memory");
}
__device__ __forceinline__ void sts_v2(uint32_t a, uint32_t v0, uint32_t v1) {
    asm volatile("st.shared.v2.u32 [%0], {%1,%2};" :: "r"(a), "r"(v0), "r"(v1) : "memory");
}
__device__ __forceinline__ uint2 lds_v2(uint32_t a) {
    uint2 r;
    asm("ld.shared.v2.u32 {%0,%1}, [%2];" : "=r"(r.x), "=r"(r.y) : "r"(a));
    return r;
}
__device__ __forceinline__ void mma_tf32(float* d, const uint32_t* a,
                                         uint32_t b0, uint32_t b1) {
    asm volatile(
        "mma.sync.aligned.m16n8k8.row.col.f32.tf32.tf32.f32 "
        "{%0,%1,%2,%3}, {%4,%5,%6,%7}, {%8,%9}, {%0,%1,%2,%3};"
        : "+f"(d[0]), "+f"(d[1]), "+f"(d[2]), "+f"(d[3])
        : "r"(a[0]), "r"(a[1]), "r"(a[2]), "r"(a[3]), "r"(b0), "r"(b1));
}

// ---------------- pass 1: idx pack + B-fragment prep (probe fused) ----------------
__global__ void __launch_bounds__(1024) pack_idx_kernel(
    const void* __restrict__ conv_, const float* __restrict__ zf,
    const float* __restrict__ wts)
{
    __shared__ int s_is64;
    if (threadIdx.x < 32) {
        int nz = (((const int*)conv_)[2 * threadIdx.x + 1] != 0);
        unsigned m = __ballot_sync(0xffffffffu, nz);
        if (threadIdx.x == 0) s_is64 = (m == 0) ? 1 : 0;
    }
    __syncthreads();
    const int is64 = s_is64;
    const int*       c32 = (const int*)conv_;
    const long long* c64 = (const long long*)conv_;

    int t = blockIdx.x * 1024 + threadIdx.x;   // 0 .. 524287

    // B fragments (first 32768 threads)
    if (t < 32768) {
        int slot = t;
        int csh = slot >> 7;
        int l   = (slot >> 2) & 31;
        int q   = slot & 3;
        int h   = csh & 1;
        int cs  = csh >> 1;
        int c   = cs >> 2, s = cs & 3;
        int j   = h * 2 + (q >> 1);
        int n   = j * 8 + (l >> 2);
        int kl  = s * 8 + ((q & 1) << 2) + (l & 3);
        g_bfrag[slot] = (kl < KL_) ? cvt_tf32(wts[n * 400 + c * KL_ + kl]) : 0u;
    }

    int l    = t & 31;
    int s    = (t >> 5) & 3;
    int wp   = (t >> 7) & 7;
    int tile = (t >> 10) & 31;
    int c    = t >> 15;
    int base = max(0, tile * 2 - 2) * W_;
    unsigned rel[4];
#pragma unroll
    for (int r = 0; r < 4; ++r) {
        int hw = tile * 128 + wp * 16 + (l >> 2) + ((r & 1) << 3);
        int k  = s * 8 + (l & 3) + ((r >> 1) << 2);
        int v  = 384;
        if (k < KL_) {
            int j = (c * HW_ + hw) * KL_ + k;
            if (zf[j] == 0.0f) {
                int raw = is64 ? (int)c64[j] : c32[j];
                v = (raw & 4095) - base;
            }
        }
        rel[r] = (unsigned)(v << 3);     // pre-scaled byte offset
    }
    ((uint2*)g_idx16)[t] = make_uint2(rel[0] | (rel[1] << 16),
                                      rel[2] | (rel[3] << 16));
}

// ---------------- SMEM layout ----------------
// B frags : [0, 65536)
// windows : ring-3, each 3104 B (385 interleaved pairs of tf32 words, pair 384 = 0)
#define SM_B       0
#define SM_WIN     65536
#define WIN_STRIDE 3104
#define SM_TOT     (65536 + 3 * WIN_STRIDE)   // 74848

// ---------------- pass 2: gather -> mma.sync tf32 ----------------
// CTA = (batch pair bp, hw tile): M = 256 (2 batches x 128 hw), 8 warps.
// 3 CTAs/SM: regs capped at 85, smem 3x74848 = 224.5 KB <= 228 KB.
__global__ void __launch_bounds__(256, 3) abc_mma_kernel(
    const float* __restrict__ x,
    float* __restrict__ out)          // (B, O, H, W)
{
    extern __shared__ char sm[];
    const int tid = threadIdx.x, wid = tid >> 5, lid = tid & 31;
    const int bp     = blockIdx.x >> 5;
    const int tile   = blockIdx.x & 31;
    const int hwbase = tile << 7;
    const int r0     = max(0, tile * 2 - 2);
    const int r1     = min(H_ - 1, tile * 2 + 3);
    const int nwords = (r1 - r0 + 1) * W_;       // 256 or 384
    const int b0     = bp * 2;

    const uint32_t b_sm   = smem_u32(sm + SM_B);
    const uint32_t win_sm = smem_u32(sm + SM_WIN);

    // async-load prebuilt B fragments (64 KB)
    {
        const char* gb = (const char*)g_bfrag;
#pragma unroll
        for (int i = 0; i < 16; ++i)
            cpasync16(b_sm + tid * 16 + i * 4096, gb + tid * 16 + i * 4096);
        asm volatile("cp.async.commit_group;" ::: "memory");
    }
    // zero the sentinel pair (word index 384) of each ring window
    if (tid < 6)
        *(float*)(sm + SM_WIN + (tid >> 1) * WIN_STRIDE + 3072 + (tid & 1) * 4) = 0.0f;

    const float* xpa = x + (((size_t)b0 * C_) << 12) + r0 * W_;
    const float* xpb = x + (((size_t)(b0 + 1) * C_) << 12) + r0 * W_;
    const bool w1ok = (tid + 256) < nwords;

    float xa0, xa1 = 0.f, xb0, xb1 = 0.f;
    // stage channel 0
    xa0 = xpa[tid]; xb0 = xpb[tid];
    if (w1ok) { xa1 = xpa[tid + 256]; xb1 = xpb[tid + 256]; }
    {
        uint32_t wa = win_sm + tid * 8;
        sts_v2(wa, cvt_tf32(xa0), cvt_tf32(xb0));
        if (w1ok) sts_v2(wa + 2048, cvt_tf32(xa1), cvt_tf32(xb1));
    }
    // preload channel 1 into regs
    xa0 = xpa[(1 << 12) + tid]; xb0 = xpb[(1 << 12) + tid];
    if (w1ok) { xa1 = xpa[(1 << 12) + tid + 256]; xb1 = xpb[(1 << 12) + tid + 256]; }

    const uint2* idxw = (const uint2*)g_idx16 + ((size_t)(tile * 8 + wid) * 4) * 32 + lid;
    uint2 ivc[4], ivn[4];
#pragma unroll
    for (int s = 0; s < 4; ++s) ivc[s] = __ldg(idxw + s * 32);

    float acc[2][4][4];
#pragma unroll
    for (int mt = 0; mt < 2; ++mt)
#pragma unroll
        for (int j = 0; j < 4; ++j)
#pragma unroll
            for (int r = 0; r < 4; ++r) acc[mt][j][r] = 0.0f;

    asm volatile("cp.async.wait_group 0;" ::: "memory");
    __syncthreads();   // win0 + B ready

#pragma unroll 1
    for (int c = 0; c < C_; ++c) {
        const int cn = c + 1;
        // stage channel c+1 (regs already hold it) into ring slot (c+1)%3
        if (cn < C_) {
            uint32_t wa = win_sm + (cn % 3) * WIN_STRIDE + tid * 8;
            sts_v2(wa, cvt_tf32(xa0), cvt_tf32(xb0));
            if (w1ok) sts_v2(wa + 2048, cvt_tf32(xa1), cvt_tf32(xb1));
        }
        // issue loads for channel c+2
        if (c + 2 < C_) {
            const int ofs = (c + 2) << 12;
            xa0 = xpa[ofs + tid]; xb0 = xpb[ofs + tid];
            if (w1ok) { xa1 = xpa[ofs + tid + 256]; xb1 = xpb[ofs + tid + 256]; }
        }
        // prefetch idx for channel c+1
        if (cn < C_) {
#pragma unroll
            for (int s = 0; s < 4; ++s)
                ivn[s] = __ldg(idxw + (size_t)cn * 32768 + s * 32);
        }
        __syncthreads();   // win[(c)%3] written (prev iter), ring-3 reuse safe

        const uint4* Bp = (const uint4*)(sm + SM_B + c * 4096);
        const uint32_t wbase = win_sm + (c % 3) * WIN_STRIDE;
#pragma unroll
        for (int s = 0; s < 4; ++s) {
            uint2 iv = ivc[s];
            uint2 p0 = lds_v2(wbase + (iv.x & 0xFFFF));
            uint2 p1 = lds_v2(wbase + (iv.x >> 16));
            uint2 p2 = lds_v2(wbase + (iv.y & 0xFFFF));
            uint2 p3 = lds_v2(wbase + (iv.y >> 16));
            uint32_t a0[4] = { p0.x, p1.x, p2.x, p3.x };
            uint32_t a1[4] = { p0.y, p1.y, p2.y, p3.y };
            uint4 bf0 = Bp[(s * 2 + 0) * 32 + lid];   // LDS.128 inline (no hoist)
            uint4 bf1 = Bp[(s * 2 + 1) * 32 + lid];
            mma_tf32(acc[0][0], a0, bf0.x, bf0.y);
            mma_tf32(acc[0][1], a0, bf0.z, bf0.w);
            mma_tf32(acc[0][2], a0, bf1.x, bf1.y);
            mma_tf32(acc[0][3], a0, bf1.z, bf1.w);
            mma_tf32(acc[1][0], a1, bf0.x, bf0.y);
            mma_tf32(acc[1][1], a1, bf0.z, bf0.w);
            mma_tf32(acc[1][2], a1, bf1.x, bf1.y);
            mma_tf32(acc[1][3], a1, bf1.z, bf1.w);
        }
#pragma unroll
        for (int s = 0; s < 4; ++s) ivc[s] = ivn[s];
    }

    // ---------------- epilogue: regs -> SMEM pad-260 -> STG.128 ----------------
    __syncthreads();
    float* ep = (float*)sm;
#pragma unroll
    for (int mt = 0; mt < 2; ++mt) {
#pragma unroll
        for (int j = 0; j < 4; ++j) {
            int nb = j * 8 + (lid & 3) * 2;
            int mb = mt * 128 + wid * 16 + (lid >> 2);
            ep[(nb + 0) * 260 + mb]     = acc[mt][j][0];
            ep[(nb + 1) * 260 + mb]     = acc[mt][j][1];
            ep[(nb + 0) * 260 + mb + 8] = acc[mt][j][2];
            ep[(nb + 1) * 260 + mb + 8] = acc[mt][j][3];
        }
    }
    __syncthreads();
    {
        int n = tid >> 3, q = tid & 7;
        int bat = q >> 2;
        const float4* src = (const float4*)(ep + n * 260 + q * 32);
        float4* dst = (float4*)(out + ((size_t)(b0 + bat) << 17)
                                + n * HW_ + hwbase + (q & 3) * 32);
#pragma unroll
        for (int i = 0; i < 8; ++i) dst[i] = src[i];
    }
}

extern "C" void kernel_launch(void* const* d_in, const int* in_sizes, int n_in,
                              void* d_out, int out_size)
{
    const float* x    = (const float*)d_in[0];
    const void*  conv = d_in[1];
    const float* zf   = (const float*)d_in[2];
    const float* wts  = (const float*)d_in[3];
    float*       out  = (float*)d_out;

    pack_idx_kernel<<<512, 1024>>>(conv, zf, wts);

    cudaFuncSetAttribute(abc_mma_kernel,
                         cudaFuncAttributeMaxDynamicSharedMemorySize, SM_TOT);
    abc_mma_kernel<<<256, 256, SM_TOT>>>(x, out);
}

// round 9
// speedup vs baseline: 1.0941x; 1.0941x over previous
#include <cuda_runtime.h>
#include <cstdint>

#define C_   16
#define H_   64
#define W_   64
#define KL_  25
#define O_   32
#define HW_  4096

// Fragment-ordered idx: [c][trow64][warp8][s2][lane32][8 u16]; u16 = word*4 (byte
// offset into window), word in [0,320], 320 = zero sentinel.  8 MB.
__device__ __align__(16) unsigned short g_idxf[16 * 64 * 8 * 2 * 32 * 8];
// Pre-built fp16x2 B fragments: [c][s][hp][lane][4 u32] = 32 KB
__device__ __align__(16) uint32_t g_bfrag16[8192];

__device__ __forceinline__ uint32_t smem_u32(const void* p) {
    uint32_t a;
    asm("{ .reg .u64 t; cvta.to.shared.u64 t, %1; cvt.u32.u64 %0, t; }" : "=r"(a) : "l"(p));
    return a;
}
__device__ __forceinline__ void cpasync16(uint32_t dst, const void* src) {
    asm volatile("cp.async.ca.shared.global [%0], [%1], 16;" :: "r"(dst), "l"(src) : "memory");
}
__device__ __forceinline__ uint32_t f16x2_pack(float lo, float hi) {
    uint32_t r;  // cvt.f16x2.f32 d, a, b -> d.hi = a, d.lo = b
    asm("cvt.rn.f16x2.f32 %0, %1, %2;" : "=r"(r) : "f"(hi), "f"(lo));
    return r;
}
__device__ __forceinline__ void sts32(uint32_t a, uint32_t v) {
    asm volatile("st.shared.u32 [%0], %1;" :: "r"(a), "r"(v) : "memory");
}
__device__ __forceinline__ uint32_t lds32(uint32_t a) {
    uint32_t r;
    asm("ld.shared.u32 %0, [%1];" : "=r"(r) : "r"(a));
    return r;
}
__device__ __forceinline__ uint32_t prmt(uint32_t a, uint32_t b, uint32_t c) {
    uint32_t d;
    asm("prmt.b32 %0, %1, %2, %3;" : "=r"(d) : "r"(a), "r"(b), "r"(c));
    return d;
}
__device__ __forceinline__ void mma_f16(float* d, const uint32_t* a,
                                        uint32_t b0, uint32_t b1) {
    asm volatile(
        "mma.sync.aligned.m16n8k16.row.col.f32.f16.f16.f32 "
        "{%0,%1,%2,%3}, {%4,%5,%6,%7}, {%8,%9}, {%0,%1,%2,%3};"
        : "+f"(d[0]), "+f"(d[1]), "+f"(d[2]), "+f"(d[3])
        : "r"(a[0]), "r"(a[1]), "r"(a[2]), "r"(a[3]), "r"(b0), "r"(b1));
}

// ---------------- pass 1: fragment idx pack + fp16 B fragments (probe fused) ----
__global__ void __launch_bounds__(1024) pack_idx_kernel(
    const void* __restrict__ conv_, const float* __restrict__ zf,
    const float* __restrict__ wts)
{
    __shared__ int s_is64;
    if (threadIdx.x < 32) {
        int nz = (((const int*)conv_)[2 * threadIdx.x + 1] != 0);
        unsigned m = __ballot_sync(0xffffffffu, nz);
        if (threadIdx.x == 0) s_is64 = (m == 0) ? 1 : 0;
    }
    __syncthreads();
    const int is64 = s_is64;
    const int*       c32p = (const int*)conv_;
    const long long* c64p = (const long long*)conv_;

    int t = blockIdx.x * 1024 + threadIdx.x;   // 0 .. 524287

    // B fragments (first 8192 threads): fp16x2 {w[n][k], w[n][k+1]}
    if (t < 8192) {
        int q = t & 3, lane = (t >> 2) & 31, hp = (t >> 7) & 1;
        int s = (t >> 8) & 1, c = t >> 9;
        int nt = hp * 2 + (q >> 1), br = q & 1;
        int n  = nt * 8 + (lane >> 2);
        int kk = 16 * s + 2 * (lane & 3) + br * 8;
        float lo = (kk     < KL_) ? wts[n * 400 + c * KL_ + kk]     : 0.f;
        float hi = (kk + 1 < KL_) ? wts[n * 400 + c * KL_ + kk + 1] : 0.f;
        g_bfrag16[t] = f16x2_pack(lo, hi);
    }

    int lane = t & 31;
    int s    = (t >> 5) & 1;
    int wp   = (t >> 6) & 7;
    int trow = (t >> 9) & 63;
    int c    = t >> 15;
    int base = max(0, trow - 2) * W_;
    int r  = lane >> 2, c4 = lane & 3;

    unsigned short v[8];
#pragma unroll
    for (int q = 0; q < 4; ++q) {
#pragma unroll
        for (int h = 0; h < 2; ++h) {
            int mrow = 16 * wp + r + ((q & 1) << 3);
            int hw   = trow * 64 + (mrow >> 1);
            int k    = 16 * s + 2 * c4 + h + ((q & 2) << 2);
            int val  = 320;
            if (k < KL_) {
                int j = (c * HW_ + hw) * KL_ + k;
                if (zf[j] == 0.0f) {
                    int raw = is64 ? (int)c64p[j] : c32p[j];
                    val = (raw & 4095) - base;
                }
            }
            v[q * 2 + h] = (unsigned short)(val << 2);   // byte offset
        }
    }
    ((uint4*)g_idxf)[t] = *(const uint4*)v;
}

// ---------------- SMEM layout ----------------
// B frags : [0, 32768)
// windows : ring-3 x 1296 B (321 fp16x2 words, word 320 = 0)
#define SM_B    0
#define SM_WIN  32768
#define WIN_STR 1296
#define SM_TOT  (32768 + 3 * WIN_STR)   // 36656

// ---------------- pass 2: gather -> mma.sync fp16 ----------------
// CTA = (batch pair bp, image row trow): M = 128 (m = 2*hw_local + batch).
// grid 512, 3 CTAs/SM.
__global__ void __launch_bounds__(256, 3) abc_mma_kernel(
    const float* __restrict__ x,
    float* __restrict__ out)          // (B, O, H, W)
{
    extern __shared__ char sm[];
    const int tid = threadIdx.x, wid = tid >> 5, lid = tid & 31;
    const int bp   = blockIdx.x >> 6;
    const int trow = blockIdx.x & 63;
    const int r0   = max(0, trow - 2);
    const int r1   = min(H_ - 1, trow + 2);
    const int nwords = (r1 - r0 + 1) * W_;       // 192 / 256 / 320
    const int base = r0 * W_;
    const int b0   = bp * 2;

    const uint32_t b_sm   = smem_u32(sm + SM_B);
    const uint32_t win_sm = smem_u32(sm + SM_WIN);

    // async-load fp16 B fragments (32 KB)
    {
        const char* gb = (const char*)g_bfrag16;
#pragma unroll
        for (int i = 0; i < 8; ++i)
            cpasync16(b_sm + tid * 16 + i * 4096, gb + tid * 16 + i * 4096);
        asm volatile("cp.async.commit_group;" ::: "memory");
    }
    // zero sentinel word (index 320) of each ring slot
    if (tid < 3) sts32(win_sm + tid * WIN_STR + 1280, 0u);

    const float* xpa = x + (((size_t)b0 * C_) << 12) + base;
    const float* xpb = x + (((size_t)(b0 + 1) * C_) << 12) + base;
    const bool w0 = tid < nwords;
    const bool w1 = (tid + 256) < nwords;

    float xa0 = 0.f, xb0 = 0.f, xa1 = 0.f, xb1 = 0.f;
    // stage channel 0 into ring 0
    if (w0) { xa0 = xpa[tid]; xb0 = xpb[tid]; }
    if (w1) { xa1 = xpa[tid + 256]; xb1 = xpb[tid + 256]; }
    if (w0) sts32(win_sm + tid * 4, f16x2_pack(xa0, xb0));
    if (w1) sts32(win_sm + (tid + 256) * 4, f16x2_pack(xa1, xb1));
    // preload channel 1
    if (w0) { xa0 = xpa[4096 + tid]; xb0 = xpb[4096 + tid]; }
    if (w1) { xa1 = xpa[4096 + tid + 256]; xb1 = xpb[4096 + tid + 256]; }

    // idx pointer: uint4 element (((c*64+trow)*8+wid)*2+s)*32 + lane
    const uint4* idxp = (const uint4*)g_idxf + (((size_t)trow * 8 + wid) * 2) * 32 + lid;
    uint4 ic0 = __ldg(idxp), ic1 = __ldg(idxp + 32);
    uint4 in0, in1;

    float acc[4][4];
#pragma unroll
    for (int nt = 0; nt < 4; ++nt)
#pragma unroll
        for (int rr = 0; rr < 4; ++rr) acc[nt][rr] = 0.0f;

    const uint32_t sel = ((lid >> 2) & 1) ? 0x7632u : 0x5410u;

    asm volatile("cp.async.wait_group 0;" ::: "memory");

#pragma unroll 1
    for (int c = 0; c < C_; ++c) {
        const int cn = c + 1;
        if (cn < C_) {   // stage channel c+1 (in regs) into ring (c+1)%3
            uint32_t wa = win_sm + (cn % 3) * WIN_STR;
            if (w0) sts32(wa + tid * 4, f16x2_pack(xa0, xb0));
            if (w1) sts32(wa + (tid + 256) * 4, f16x2_pack(xa1, xb1));
        }
        if (c + 2 < C_) {   // issue loads for channel c+2
            const int ofs = (c + 2) << 12;
            if (w0) { xa0 = xpa[ofs + tid]; xb0 = xpb[ofs + tid]; }
            if (w1) { xa1 = xpa[ofs + tid + 256]; xb1 = xpb[ofs + tid + 256]; }
        }
        if (cn < C_) {   // prefetch idx for channel c+1
            in0 = __ldg(idxp + (size_t)cn * 32768);
            in1 = __ldg(idxp + (size_t)cn * 32768 + 32);
        }
        __syncthreads();   // ring-3 reuse safety (same proof as R7)

        // hoist B fragments: 4 independent LDS.128
        const uint4* Bp = (const uint4*)(sm + SM_B) + c * 128;
        uint4 Bf00 = Bp[lid], Bf01 = Bp[32 + lid];
        uint4 Bf10 = Bp[64 + lid], Bf11 = Bp[96 + lid];

        const uint32_t wbase = win_sm + (c % 3) * WIN_STR;
        {   // s = 0
            uint32_t a[4];
            a[0] = prmt(lds32(wbase + (ic0.x & 0xFFFF)), lds32(wbase + (ic0.x >> 16)), sel);
            a[1] = prmt(lds32(wbase + (ic0.y & 0xFFFF)), lds32(wbase + (ic0.y >> 16)), sel);
            a[2] = prmt(lds32(wbase + (ic0.z & 0xFFFF)), lds32(wbase + (ic0.z >> 16)), sel);
            a[3] = prmt(lds32(wbase + (ic0.w & 0xFFFF)), lds32(wbase + (ic0.w >> 16)), sel);
            mma_f16(acc[0], a, Bf00.x, Bf00.y);
            mma_f16(acc[1], a, Bf00.z, Bf00.w);
            mma_f16(acc[2], a, Bf01.x, Bf01.y);
            mma_f16(acc[3], a, Bf01.z, Bf01.w);
        }
        {   // s = 1
            uint32_t a[4];
            a[0] = prmt(lds32(wbase + (ic1.x & 0xFFFF)), lds32(wbase + (ic1.x >> 16)), sel);
            a[1] = prmt(lds32(wbase + (ic1.y & 0xFFFF)), lds32(wbase + (ic1.y >> 16)), sel);
            a[2] = prmt(lds32(wbase + (ic1.z & 0xFFFF)), lds32(wbase + (ic1.z >> 16)), sel);
            a[3] = prmt(lds32(wbase + (ic1.w & 0xFFFF)), lds32(wbase + (ic1.w >> 16)), sel);
            mma_f16(acc[0], a, Bf10.x, Bf10.y);
            mma_f16(acc[1], a, Bf10.z, Bf10.w);
            mma_f16(acc[2], a, Bf11.x, Bf11.y);
            mma_f16(acc[3], a, Bf11.z, Bf11.w);
        }
        ic0 = in0; ic1 = in1;
    }

    // ---------------- epilogue: regs -> SMEM [n:136][bat:68][hw] -> STG.128 ------
    __syncthreads();
    float* ep = (float*)sm;
#pragma unroll
    for (int nt = 0; nt < 4; ++nt) {
#pragma unroll
        for (int rg = 0; rg < 4; ++rg) {
            int n    = nt * 8 + 2 * (lid & 3) + (rg & 1);
            int mrow = 16 * wid + (lid >> 2) + ((rg & 2) << 2);
            ep[n * 136 + (mrow & 1) * 68 + (mrow >> 1)] = acc[nt][rg];
        }
    }
    __syncthreads();
    {
        int n = tid >> 3, sub = tid & 7;
        int bat = sub >> 2, ch = sub & 3;
        const float4* src = (const float4*)(ep + n * 136 + bat * 68 + ch * 16);
        float4* dst = (float4*)(out + (((size_t)(b0 + bat) * O_ + n) << 12)
                                + trow * 64 + ch * 16);
#pragma unroll
        for (int i = 0; i < 4; ++i) dst[i] = src[i];
    }
}

extern "C" void kernel_launch(void* const* d_in, const int* in_sizes, int n_in,
                              void* d_out, int out_size)
{
    const float* x    = (const float*)d_in[0];
    const void*  conv = d_in[1];
    const float* zf   = (const float*)d_in[2];
    const float* wts  = (const float*)d_in[3];
    float*       out  = (float*)d_out;

    pack_idx_kernel<<<512, 1024>>>(conv, zf, wts);
    abc_mma_kernel<<<512, 256, SM_TOT>>>(x, out);
}

// round 10
// speedup vs baseline: 1.3782x; 1.2597x over previous
#include <cuda_runtime.h>
#include <cstdint>

#define C_   16
#define H_   64
#define W_   64
#define KL_  25
#define O_   32
#define HW_  4096

// Fragment-ordered idx for grid-256 tiling:
// uint4 e = ((((c*32+tile)*8+w)*2+T)*2+s)*32 + lane ; 8 u16 byte offsets
// (word*4) into the tile's channel window; word in [0,384), sentinel 384. 16 MB.
__device__ __align__(16) unsigned short g_idxf[16 * 32 * 8 * 2 * 2 * 32 * 8];
// Pre-built fp16x2 B fragments: [c][s][hp][lane][4 u32] = 32 KB (R9-proven layout)
__device__ __align__(16) uint32_t g_bfrag16[8192];

__device__ __forceinline__ uint32_t smem_u32(const void* p) {
    uint32_t a;
    asm("{ .reg .u64 t; cvta.to.shared.u64 t, %1; cvt.u32.u64 %0, t; }" : "=r"(a) : "l"(p));
    return a;
}
__device__ __forceinline__ void cpasync16(uint32_t dst, const void* src) {
    asm volatile("cp.async.ca.shared.global [%0], [%1], 16;" :: "r"(dst), "l"(src) : "memory");
}
__device__ __forceinline__ uint32_t f16x2_pack(float lo, float hi) {
    uint32_t r;  // d.hi = first operand, d.lo = second
    asm("cvt.rn.f16x2.f32 %0, %1, %2;" : "=r"(r) : "f"(hi), "f"(lo));
    return r;
}
__device__ __forceinline__ void sts32(uint32_t a, uint32_t v) {
    asm volatile("st.shared.u32 [%0], %1;" :: "r"(a), "r"(v) : "memory");
}
__device__ __forceinline__ void sts128(uint32_t a, uint32_t v0, uint32_t v1,
                                       uint32_t v2, uint32_t v3) {
    asm volatile("st.shared.v4.b32 [%0], {%1,%2,%3,%4};"
                 :: "r"(a), "r"(v0), "r"(v1), "r"(v2), "r"(v3) : "memory");
}
__device__ __forceinline__ uint32_t lds32(uint32_t a) {
    uint32_t r;
    asm("ld.shared.u32 %0, [%1];" : "=r"(r) : "r"(a));
    return r;
}
__device__ __forceinline__ uint32_t prmt(uint32_t a, uint32_t b, uint32_t c) {
    uint32_t d;
    asm("prmt.b32 %0, %1, %2, %3;" : "=r"(d) : "r"(a), "r"(b), "r"(c));
    return d;
}
__device__ __forceinline__ void mma_f16(float* d, const uint32_t* a,
                                        uint32_t b0, uint32_t b1) {
    asm volatile(
        "mma.sync.aligned.m16n8k16.row.col.f32.f16.f16.f32 "
        "{%0,%1,%2,%3}, {%4,%5,%6,%7}, {%8,%9}, {%0,%1,%2,%3};"
        : "+f"(d[0]), "+f"(d[1]), "+f"(d[2]), "+f"(d[3])
        : "r"(a[0]), "r"(a[1]), "r"(a[2]), "r"(a[3]), "r"(b0), "r"(b1));
}

// ---------------- pass 1: fragment idx pack + fp16 B fragments (probe fused) ----
__global__ void __launch_bounds__(1024) pack_idx_kernel(
    const void* __restrict__ conv_, const float* __restrict__ zf,
    const float* __restrict__ wts)
{
    __shared__ int s_is64;
    if (threadIdx.x < 32) {
        int nz = (((const int*)conv_)[2 * threadIdx.x + 1] != 0);
        unsigned m = __ballot_sync(0xffffffffu, nz);
        if (threadIdx.x == 0) s_is64 = (m == 0) ? 1 : 0;
    }
    __syncthreads();
    const int is64 = s_is64;
    const int*       c32p = (const int*)conv_;
    const long long* c64p = (const long long*)conv_;

    int t = blockIdx.x * 1024 + threadIdx.x;   // 0 .. 524287

    // B fragments (first 8192 threads): fp16x2 {w[n][k], w[n][k+1]} (R9-proven)
    if (t < 8192) {
        int q = t & 3, lane = (t >> 2) & 31, hp = (t >> 7) & 1;
        int s = (t >> 8) & 1, c = t >> 9;
        int nt = hp * 2 + (q >> 1), br = q & 1;
        int n  = nt * 8 + (lane >> 2);
        int kk = 16 * s + 2 * (lane & 3) + br * 8;
        float lo = (kk     < KL_) ? wts[n * 400 + c * KL_ + kk]     : 0.f;
        float hi = (kk + 1 < KL_) ? wts[n * 400 + c * KL_ + kk + 1] : 0.f;
        g_bfrag16[t] = f16x2_pack(lo, hi);
    }

    int lane = t & 31;
    int s    = (t >> 5) & 1;
    int T    = (t >> 6) & 1;
    int w    = (t >> 7) & 7;
    int tile = (t >> 10) & 31;
    int c    = t >> 15;
    int base = max(0, tile * 2 - 2) * W_;
    int r  = lane >> 2, c4 = lane & 3;

    unsigned short v[8];
#pragma unroll
    for (int q = 0; q < 4; ++q) {
#pragma unroll
        for (int h = 0; h < 2; ++h) {
            int mrow = 16 * T + r + 8 * (q & 1);     // within warp's 32-row region
            int hw   = tile * 128 + 16 * w + (mrow >> 1);
            int k    = 16 * s + 2 * c4 + h + ((q & 2) << 2);
            int val  = 384;
            if (k < KL_) {
                int j = (c * HW_ + hw) * KL_ + k;
                if (zf[j] == 0.0f) {
                    int raw = is64 ? (int)c64p[j] : c32p[j];
                    val = (raw & 4095) - base;       // in [0, 384)
                }
            }
            v[q * 2 + h] = (unsigned short)(val << 2);
        }
    }
    ((uint4*)g_idxf)[t] = *(const uint4*)v;
}

// ---------------- SMEM layout ----------------
// B frags : [0, 32768)
// windows : 16 channels x 1552 B (388 fp16x2 words; word 384 = 0 sentinel)
#define SM_B     0
#define SM_WIN   32768
#define WIN_STR  1552
#define SM_TOT   (32768 + 16 * WIN_STR)    // 57600

// ---------------- pass 2: barrier-free gather -> mma.sync fp16 ----------------
// CTA = (batch pair bp, 128-hw tile): M = 256 (m = 2*hwloc + batch). grid 256.
__global__ void __launch_bounds__(256, 2) abc_mma_kernel(
    const float* __restrict__ x,
    float* __restrict__ out)          // (B, O, H, W)
{
    extern __shared__ char sm[];
    const int tid = threadIdx.x, wid = tid >> 5, lid = tid & 31;
    const int bp     = blockIdx.x >> 5;
    const int tile   = blockIdx.x & 31;
    const int r0     = max(0, tile * 2 - 2);
    const int r1     = min(H_ - 1, tile * 2 + 3);
    const int nwords = (r1 - r0 + 1) * W_;        // 256 or 384
    const int b0     = bp * 2;

    const uint32_t b_sm   = smem_u32(sm + SM_B);
    const uint32_t win_sm = smem_u32(sm + SM_WIN);

    // async-load fp16 B fragments (32 KB)
    {
        const char* gb = (const char*)g_bfrag16;
#pragma unroll
        for (int i = 0; i < 8; ++i)
            cpasync16(b_sm + tid * 16 + i * 4096, gb + tid * 16 + i * 4096);
        asm volatile("cp.async.commit_group;" ::: "memory");
    }
    // zero sentinel word (index 384) of every channel window
    if (tid < 16) sts32(win_sm + tid * WIN_STR + 1536, 0u);

    // ---- stage ALL 16 channel windows (both batches packed fp16x2) ----
    {
        const float4* pa = (const float4*)(x + (((size_t)b0 * C_) << 12) + r0 * W_);
        const float4* pb = (const float4*)(x + (((size_t)(b0 + 1) * C_) << 12) + r0 * W_);
#pragma unroll
        for (int it = 0; it < 6; ++it) {
            int i4 = tid + it * 256;              // 0..1535 over 16ch x 96 float4
            int ch = i4 / 96;
            int wg = i4 - ch * 96;
            if (wg * 4 < nwords) {
                float4 va = __ldg(pa + (ch << 10) + wg);
                float4 vb = __ldg(pb + (ch << 10) + wg);
                sts128(win_sm + ch * WIN_STR + wg * 16,
                       f16x2_pack(va.x, vb.x), f16x2_pack(va.y, vb.y),
                       f16x2_pack(va.z, vb.z), f16x2_pack(va.w, vb.w));
            }
        }
    }
    asm volatile("cp.async.wait_group 0;" ::: "memory");
    __syncthreads();   // the ONLY mainloop barrier

    // idx pointers: uint4 e = (((c*32+tile)*8+wid)*2+T)*2+s)*32 + lane
    const uint4* idxp = (const uint4*)g_idxf + ((size_t)(tile * 8 + wid) * 4) * 32 + lid;
    uint4 ic[4], in_[4];
#pragma unroll
    for (int j = 0; j < 4; ++j) ic[j] = __ldg(idxp + j * 32);

    float acc[2][4][4];
#pragma unroll
    for (int T = 0; T < 2; ++T)
#pragma unroll
        for (int nt = 0; nt < 4; ++nt)
#pragma unroll
            for (int rr = 0; rr < 4; ++rr) acc[T][nt][rr] = 0.0f;

    const uint32_t sel = ((lid >> 2) & 1) ? 0x7632u : 0x5410u;

#pragma unroll 1
    for (int c = 0; c < C_; ++c) {
        if (c + 1 < C_) {
#pragma unroll
            for (int j = 0; j < 4; ++j)
                in_[j] = __ldg(idxp + (size_t)(c + 1) * 32768 + j * 32);
        }
        const uint4* Bp = (const uint4*)(sm + SM_B) + c * 128;
        uint4 Bf0 = Bp[lid], Bf1 = Bp[32 + lid];
        uint4 Bf2 = Bp[64 + lid], Bf3 = Bp[96 + lid];

        const uint32_t wbase = win_sm + c * WIN_STR;
#pragma unroll
        for (int T = 0; T < 2; ++T) {
            {   // s = 0
                uint4 iv = ic[T * 2];
                uint32_t a[4];
                a[0] = prmt(lds32(wbase + (iv.x & 0xFFFF)), lds32(wbase + (iv.x >> 16)), sel);
                a[1] = prmt(lds32(wbase + (iv.y & 0xFFFF)), lds32(wbase + (iv.y >> 16)), sel);
                a[2] = prmt(lds32(wbase + (iv.z & 0xFFFF)), lds32(wbase + (iv.z >> 16)), sel);
                a[3] = prmt(lds32(wbase + (iv.w & 0xFFFF)), lds32(wbase + (iv.w >> 16)), sel);
                mma_f16(acc[T][0], a, Bf0.x, Bf0.y);
                mma_f16(acc[T][1], a, Bf0.z, Bf0.w);
                mma_f16(acc[T][2], a, Bf1.x, Bf1.y);
                mma_f16(acc[T][3], a, Bf1.z, Bf1.w);
            }
            {   // s = 1
                uint4 iv = ic[T * 2 + 1];
                uint32_t a[4];
                a[0] = prmt(lds32(wbase + (iv.x & 0xFFFF)), lds32(wbase + (iv.x >> 16)), sel);
                a[1] = prmt(lds32(wbase + (iv.y & 0xFFFF)), lds32(wbase + (iv.y >> 16)), sel);
                a[2] = prmt(lds32(wbase + (iv.z & 0xFFFF)), lds32(wbase + (iv.z >> 16)), sel);
                a[3] = prmt(lds32(wbase + (iv.w & 0xFFFF)), lds32(wbase + (iv.w >> 16)), sel);
                mma_f16(acc[T][0], a, Bf2.x, Bf2.y);
                mma_f16(acc[T][1], a, Bf2.z, Bf2.w);
                mma_f16(acc[T][2], a, Bf3.x, Bf3.y);
                mma_f16(acc[T][3], a, Bf3.z, Bf3.w);
            }
        }
#pragma unroll
        for (int j = 0; j < 4; ++j) ic[j] = in_[j];
    }

    // ---------------- epilogue: regs -> SMEM [n:264][bat:132][hwloc] -> STG.128 --
    __syncthreads();                 // windows/B done; reuse smem
    float* ep = (float*)sm;          // 32 * 264 floats = 33792 B
#pragma unroll
    for (int T = 0; T < 2; ++T) {
#pragma unroll
        for (int nt = 0; nt < 4; ++nt) {
#pragma unroll
            for (int rg = 0; rg < 4; ++rg) {
                int n    = nt * 8 + 2 * (lid & 3) + (rg & 1);
                int mrow = 16 * T + (lid >> 2) + 8 * (rg >> 1);
                int hwl  = 16 * wid + (mrow >> 1);
                ep[n * 264 + (mrow & 1) * 132 + hwl] = acc[T][nt][rg];
            }
        }
    }
    __syncthreads();
    {
        int n = tid >> 3, q = tid & 7;
        int bat = q >> 2, qq = q & 3;
        const float4* src = (const float4*)(ep + n * 264 + bat * 132 + qq * 32);
        float4* dst = (float4*)(out + (((size_t)(b0 + bat) * O_ + n) << 12)
                                + tile * 128 + qq * 32);
#pragma unroll
        for (int i = 0; i < 8; ++i) dst[i] = src[i];
    }
}

extern "C" void kernel_launch(void* const* d_in, const int* in_sizes, int n_in,
                              void* d_out, int out_size)
{
    const float* x    = (const float*)d_in[0];
    const void*  conv = d_in[1];
    const float* zf   = (const float*)d_in[2];
    const float* wts  = (const float*)d_in[3];
    float*       out  = (float*)d_out;

    pack_idx_kernel<<<512, 1024>>>(conv, zf, wts);

    cudaFuncSetAttribute(abc_mma_kernel,
                         cudaFuncAttributeMaxDynamicSharedMemorySize, SM_TOT);
    abc_mma_kernel<<<256, 256, SM_TOT>>>(x, out);
}

// round 11
// speedup vs baseline: 1.7989x; 1.3052x over previous
#include <cuda_runtime.h>
#include <cstdint>

#define C_   16
#define H_   64
#define W_   64
#define KL_  25
#define O_   32
#define HW_  4096

// Fragment-ordered idx: uint4 e = (((c*32+tile)*8+w)*2+s)*32 + lane ; 8 u16 byte
// offsets (word*4) into the tile's channel window; word in [0,384], 384 = zero
// sentinel. 4 MB.
__device__ __align__(16) unsigned short g_idxf[16 * 32 * 8 * 2 * 32 * 8];
// Pre-built fp16x2 B fragments: [c][s][hp][lane][4 u32] = 32 KB (R9-proven layout)
__device__ __align__(16) uint32_t g_bfrag16[8192];

__device__ __forceinline__ uint32_t smem_u32(const void* p) {
    uint32_t a;
    asm("{ .reg .u64 t; cvta.to.shared.u64 t, %1; cvt.u32.u64 %0, t; }" : "=r"(a) : "l"(p));
    return a;
}
__device__ __forceinline__ void cpasync16(uint32_t dst, const void* src) {
    asm volatile("cp.async.ca.shared.global [%0], [%1], 16;" :: "r"(dst), "l"(src) : "memory");
}
__device__ __forceinline__ uint32_t f16x2_pack(float lo, float hi) {
    uint32_t r;  // d.hi = first operand, d.lo = second
    asm("cvt.rn.f16x2.f32 %0, %1, %2;" : "=r"(r) : "f"(hi), "f"(lo));
    return r;
}
__device__ __forceinline__ void sts32(uint32_t a, uint32_t v) {
    asm volatile("st.shared.u32 [%0], %1;" :: "r"(a), "r"(v) : "memory");
}
__device__ __forceinline__ void sts128(uint32_t a, uint32_t v0, uint32_t v1,
                                       uint32_t v2, uint32_t v3) {
    asm volatile("st.shared.v4.b32 [%0], {%1,%2,%3,%4};"
                 :: "r"(a), "r"(v0), "r"(v1), "r"(v2), "r"(v3) : "memory");
}
__device__ __forceinline__ uint32_t lds32(uint32_t a) {
    uint32_t r;
    asm("ld.shared.u32 %0, [%1];" : "=r"(r) : "r"(a));
    return r;
}
__device__ __forceinline__ uint32_t prmt(uint32_t a, uint32_t b, uint32_t c) {
    uint32_t d;
    asm("prmt.b32 %0, %1, %2, %3;" : "=r"(d) : "r"(a), "r"(b), "r"(c));
    return d;
}
__device__ __forceinline__ void mma_f16(float* d, const uint32_t* a,
                                        uint32_t b0, uint32_t b1) {
    asm volatile(
        "mma.sync.aligned.m16n8k16.row.col.f32.f16.f16.f32 "
        "{%0,%1,%2,%3}, {%4,%5,%6,%7}, {%8,%9}, {%0,%1,%2,%3};"
        : "+f"(d[0]), "+f"(d[1]), "+f"(d[2]), "+f"(d[3])
        : "r"(a[0]), "r"(a[1]), "r"(a[2]), "r"(a[3]), "r"(b0), "r"(b1));
}

// ---------------- pass 1: fragment idx pack + fp16 B fragments (probe fused) ----
// 262144 uint4 idx elements + 8192 B-fragment words. Grid 256 x 1024.
__global__ void __launch_bounds__(1024) pack_idx_kernel(
    const void* __restrict__ conv_, const float* __restrict__ zf,
    const float* __restrict__ wts)
{
    __shared__ int s_is64;
    if (threadIdx.x < 32) {
        int nz = (((const int*)conv_)[2 * threadIdx.x + 1] != 0);
        unsigned m = __ballot_sync(0xffffffffu, nz);
        if (threadIdx.x == 0) s_is64 = (m == 0) ? 1 : 0;
    }
    __syncthreads();
    const int is64 = s_is64;
    const int*       c32p = (const int*)conv_;
    const long long* c64p = (const long long*)conv_;

    int t = blockIdx.x * 1024 + threadIdx.x;   // 0 .. 262143

    // B fragments (first 8192 threads): fp16x2 {w[n][k], w[n][k+1]} (R9-proven)
    if (t < 8192) {
        int q = t & 3, lane = (t >> 2) & 31, hp = (t >> 7) & 1;
        int s = (t >> 8) & 1, c = t >> 9;
        int nt = hp * 2 + (q >> 1), br = q & 1;
        int n  = nt * 8 + (lane >> 2);
        int kk = 16 * s + 2 * (lane & 3) + br * 8;
        float lo = (kk     < KL_) ? wts[n * 400 + c * KL_ + kk]     : 0.f;
        float hi = (kk + 1 < KL_) ? wts[n * 400 + c * KL_ + kk + 1] : 0.f;
        g_bfrag16[t] = f16x2_pack(lo, hi);
    }

    int lane = t & 31;
    int s    = (t >> 5) & 1;
    int w    = (t >> 6) & 7;
    int tile = (t >> 9) & 31;
    int c    = t >> 14;
    int base = max(0, tile * 2 - 2) * W_;
    int r  = lane >> 2, c4 = lane & 3;

    unsigned short v[8];
#pragma unroll
    for (int q = 0; q < 4; ++q) {
#pragma unroll
        for (int h = 0; h < 2; ++h) {
            int row = r + 8 * (q & 1);               // 0..15 within warp tile
            int hw  = tile * 128 + 16 * w + row;
            int k   = 16 * s + 2 * c4 + h + ((q & 2) << 2);
            int val = 384;
            if (k < KL_) {
                int j = (c * HW_ + hw) * KL_ + k;
                if (zf[j] == 0.0f) {
                    int raw = is64 ? (int)c64p[j] : c32p[j];
                    val = (raw & 4095) - base;       // in [0, 384)
                }
            }
            v[q * 2 + h] = (unsigned short)(val << 2);
        }
    }
    ((uint4*)g_idxf)[t] = *(const uint4*)v;
}

// ---------------- SMEM layout ----------------
// B frags : [0, 32768)
// windows : 16 channels x 1552 B (388 fp16x2 words; word 384 = 0 sentinel)
#define SM_B     0
#define SM_WIN   32768
#define WIN_STR  1552
#define SM_TOT   (32768 + 16 * WIN_STR)    // 57600

// ---------------- pass 2: barrier-free gather -> mma.sync fp16 ----------------
// CTA = (batch pair bp, 128-hw tile): M = 128 hw; both batches via packed fp16x2
// windows, split into per-batch A fragments by PRMT (both halves consumed).
__global__ void __launch_bounds__(256, 2) abc_mma_kernel(
    const float* __restrict__ x,
    float* __restrict__ out)          // (B, O, H, W)
{
    extern __shared__ char sm[];
    const int tid = threadIdx.x, wid = tid >> 5, lid = tid & 31;
    const int bp     = blockIdx.x >> 5;
    const int tile   = blockIdx.x & 31;
    const int r0     = max(0, tile * 2 - 2);
    const int r1     = min(H_ - 1, tile * 2 + 3);
    const int nwords = (r1 - r0 + 1) * W_;        // 256 or 384
    const int b0     = bp * 2;

    const uint32_t b_sm   = smem_u32(sm + SM_B);
    const uint32_t win_sm = smem_u32(sm + SM_WIN);

    // async-load fp16 B fragments (32 KB)
    {
        const char* gb = (const char*)g_bfrag16;
#pragma unroll
        for (int i = 0; i < 8; ++i)
            cpasync16(b_sm + tid * 16 + i * 4096, gb + tid * 16 + i * 4096);
        asm volatile("cp.async.commit_group;" ::: "memory");
    }
    // zero sentinel word (index 384) of every channel window
    if (tid < 16) sts32(win_sm + tid * WIN_STR + 1536, 0u);

    // ---- stage ALL 16 channel windows (both batches packed fp16x2) ----
    {
        const float4* pa = (const float4*)(x + (((size_t)b0 * C_) << 12) + r0 * W_);
        const float4* pb = (const float4*)(x + (((size_t)(b0 + 1) * C_) << 12) + r0 * W_);
#pragma unroll
        for (int it = 0; it < 6; ++it) {
            int i4 = tid + it * 256;              // 0..1535 over 16ch x 96 float4
            int ch = i4 / 96;
            int wg = i4 - ch * 96;
            if (wg * 4 < nwords) {
                float4 va = __ldg(pa + (ch << 10) + wg);
                float4 vb = __ldg(pb + (ch << 10) + wg);
                sts128(win_sm + ch * WIN_STR + wg * 16,
                       f16x2_pack(va.x, vb.x), f16x2_pack(va.y, vb.y),
                       f16x2_pack(va.z, vb.z), f16x2_pack(va.w, vb.w));
            }
        }
    }
    asm volatile("cp.async.wait_group 0;" ::: "memory");
    __syncthreads();   // the ONLY mainloop barrier

    // idx pointers: uint4 e = ((c*256 + tile*8 + wid)*2 + s)*32 + lane
    const uint4* idxp = (const uint4*)g_idxf + ((size_t)(tile * 8 + wid) * 2) * 32 + lid;
    uint4 ic[2], in_[2];
    ic[0] = __ldg(idxp);
    ic[1] = __ldg(idxp + 32);

    float acc[2][4][4];
#pragma unroll
    for (int bt = 0; bt < 2; ++bt)
#pragma unroll
        for (int nt = 0; nt < 4; ++nt)
#pragma unroll
            for (int rr = 0; rr < 4; ++rr) acc[bt][nt][rr] = 0.0f;

#pragma unroll 1
    for (int c = 0; c < C_; ++c) {
        if (c + 1 < C_) {
            in_[0] = __ldg(idxp + (size_t)(c + 1) * 16384);
            in_[1] = __ldg(idxp + (size_t)(c + 1) * 16384 + 32);
        }
        const uint4* Bp = (const uint4*)(sm + SM_B) + c * 128;
        uint4 Bf0 = Bp[lid], Bf1 = Bp[32 + lid];       // s=0: hp0, hp1
        uint4 Bf2 = Bp[64 + lid], Bf3 = Bp[96 + lid];  // s=1: hp0, hp1

        const uint32_t wbase = win_sm + c * WIN_STR;
        {   // s = 0
            uint4 iv = ic[0];
            uint32_t aA[4], aB[4], w0, w1;
            w0 = lds32(wbase + (iv.x & 0xFFFF)); w1 = lds32(wbase + (iv.x >> 16));
            aA[0] = prmt(w0, w1, 0x5410u); aB[0] = prmt(w0, w1, 0x7632u);
            w0 = lds32(wbase + (iv.y & 0xFFFF)); w1 = lds32(wbase + (iv.y >> 16));
            aA[1] = prmt(w0, w1, 0x5410u); aB[1] = prmt(w0, w1, 0x7632u);
            w0 = lds32(wbase + (iv.z & 0xFFFF)); w1 = lds32(wbase + (iv.z >> 16));
            aA[2] = prmt(w0, w1, 0x5410u); aB[2] = prmt(w0, w1, 0x7632u);
            w0 = lds32(wbase + (iv.w & 0xFFFF)); w1 = lds32(wbase + (iv.w >> 16));
            aA[3] = prmt(w0, w1, 0x5410u); aB[3] = prmt(w0, w1, 0x7632u);
            mma_f16(acc[0][0], aA, Bf0.x, Bf0.y);
            mma_f16(acc[0][1], aA, Bf0.z, Bf0.w);
            mma_f16(acc[0][2], aA, Bf1.x, Bf1.y);
            mma_f16(acc[0][3], aA, Bf1.z, Bf1.w);
            mma_f16(acc[1][0], aB, Bf0.x, Bf0.y);
            mma_f16(acc[1][1], aB, Bf0.z, Bf0.w);
            mma_f16(acc[1][2], aB, Bf1.x, Bf1.y);
            mma_f16(acc[1][3], aB, Bf1.z, Bf1.w);
        }
        {   // s = 1
            uint4 iv = ic[1];
            uint32_t aA[4], aB[4], w0, w1;
            w0 = lds32(wbase + (iv.x & 0xFFFF)); w1 = lds32(wbase + (iv.x >> 16));
            aA[0] = prmt(w0, w1, 0x5410u); aB[0] = prmt(w0, w1, 0x7632u);
            w0 = lds32(wbase + (iv.y & 0xFFFF)); w1 = lds32(wbase + (iv.y >> 16));
            aA[1] = prmt(w0, w1, 0x5410u); aB[1] = prmt(w0, w1, 0x7632u);
            w0 = lds32(wbase + (iv.z & 0xFFFF)); w1 = lds32(wbase + (iv.z >> 16));
            aA[2] = prmt(w0, w1, 0x5410u); aB[2] = prmt(w0, w1, 0x7632u);
            w0 = lds32(wbase + (iv.w & 0xFFFF)); w1 = lds32(wbase + (iv.w >> 16));
            aA[3] = prmt(w0, w1, 0x5410u); aB[3] = prmt(w0, w1, 0x7632u);
            mma_f16(acc[0][0], aA, Bf2.x, Bf2.y);
            mma_f16(acc[0][1], aA, Bf2.z, Bf2.w);
            mma_f16(acc[0][2], aA, Bf3.x, Bf3.y);
            mma_f16(acc[0][3], aA, Bf3.z, Bf3.w);
            mma_f16(acc[1][0], aB, Bf2.x, Bf2.y);
            mma_f16(acc[1][1], aB, Bf2.z, Bf2.w);
            mma_f16(acc[1][2], aB, Bf3.x, Bf3.y);
            mma_f16(acc[1][3], aB, Bf3.z, Bf3.w);
        }
        ic[0] = in_[0]; ic[1] = in_[1];
    }

    // ---------------- epilogue: regs -> SMEM [n:264][bat:132][hwl] -> STG.128 ----
    __syncthreads();                 // windows/B done; reuse smem
    float* ep = (float*)sm;          // 32 * 264 floats = 33792 B
#pragma unroll
    for (int bt = 0; bt < 2; ++bt) {
#pragma unroll
        for (int nt = 0; nt < 4; ++nt) {
#pragma unroll
            for (int rg = 0; rg < 4; ++rg) {
                int n   = nt * 8 + 2 * (lid & 3) + (rg & 1);
                int hwl = 16 * wid + (lid >> 2) + 8 * (rg >> 1);
                ep[n * 264 + bt * 132 + hwl] = acc[bt][nt][rg];
            }
        }
    }
    __syncthreads();
    {
        int n = tid >> 3, q = tid & 7;
        int bat = q >> 2, qq = q & 3;
        const float4* src = (const float4*)(ep + n * 264 + bat * 132 + qq * 32);
        float4* dst = (float4*)(out + (((size_t)(b0 + bat) * O_ + n) << 12)
                                + tile * 128 + qq * 32);
#pragma unroll
        for (int i = 0; i < 8; ++i) dst[i] = src[i];
    }
}

extern "C" void kernel_launch(void* const* d_in, const int* in_sizes, int n_in,
                              void* d_out, int out_size)
{
    const float* x    = (const float*)d_in[0];
    const void*  conv = d_in[1];
    const float* zf   = (const float*)d_in[2];
    const float* wts  = (const float*)d_in[3];
    float*       out  = (float*)d_out;

    pack_idx_kernel<<<256, 1024>>>(conv, zf, wts);

    cudaFuncSetAttribute(abc_mma_kernel,
                         cudaFuncAttributeMaxDynamicSharedMemorySize, SM_TOT);
    abc_mma_kernel<<<256, 256, SM_TOT>>>(x, out);
}